// round 6
// baseline (speedup 1.0000x reference)
#include <cuda_runtime.h>
#include <cstdint>

#define THREADS 256
#define NW 8            // warps per block
#define GRID 152

typedef unsigned long long ull;

__device__ __forceinline__ ull pk2(float lo, float hi) {
  ull r; asm("mov.b64 %0, {%1, %2};" : "=l"(r) : "f"(lo), "f"(hi)); return r;
}
__device__ __forceinline__ void unpk2(ull v, float& lo, float& hi) {
  asm("mov.b64 {%0, %1}, %2;" : "=f"(lo), "=f"(hi) : "l"(v));
}
__device__ __forceinline__ ull fma2(ull a, ull b, ull c) {
  ull d; asm("fma.rn.f32x2 %0, %1, %2, %3;" : "=l"(d) : "l"(a), "l"(b), "l"(c)); return d;
}

// ~149 KB dynamic shared memory, 1 block (8 warps) per SM.
struct Smem {
  // layers 1-3: row k stored qq-major: phys = qq*8 + ol*2 + par for logical
  // pair p = ol*8 + qq*2 + par. At fixed qq the warp's 4 ol-addresses are 4
  // consecutive 16B words in one 64B block -> conflict-free, static offsets.
  alignas(16) float2 Wp[3][64][32];
  alignas(16) float2 Wp4[64][20];      // layer 4: pairs 0..16 real (34 outs), 17..19 zero
  alignas(16) float2 Bp[3][32];
  alignas(16) float2 Bp4[20];
  float  cw1t[5][16];      // [q][c]
  float  cb1[16];
  float  cw2t[16][5][32];  // [ci][q][c2]
  float  cb2[32];
  float  Wo[704];
  float  bo2[2];
  alignas(16) float  H[NW][64 * 32];   // per-warp activation tile, k-major, bank-swizzled
  alignas(16) float  pooled[NW][40];
  alignas(16) float  mps[NW][16][16];  // maxpool rows padded 15->16
};

// swizzled float-index of H element (row k, float column c 0..31)
__device__ __forceinline__ int hidx(int k, int c) {
  return k * 32 + ((((c >> 2) + (k >> 4)) & 7) << 2) + (c & 3);
}

// Layers 1-3: warp covers 32 nodes x 64 outputs; lane tile = 4 nodes x 8 pairs.
__device__ __forceinline__ void mlp8x4(const float2* __restrict__ Wk,  // [64][32] qq-major
                                       const float2* __restrict__ Bp,  // [32] logical order
                                       float* __restrict__ Hw,         // [64*32]
                                       int nl, int ol) {
  ull acc[4][8];
#pragma unroll
  for (int p = 0; p < 8; p++) {
    float2 b = Bp[8 * ol + p];
    ull bb = pk2(b.x, b.y);
#pragma unroll
    for (int n = 0; n < 4; n++) acc[n][p] = bb;
  }
#pragma unroll 8
  for (int k = 0; k < 64; k++) {
    const float4 hv = *reinterpret_cast<const float4*>(Hw + hidx(k, 4 * nl));
    ull hd0 = pk2(hv.x, hv.x), hd1 = pk2(hv.y, hv.y);
    ull hd2 = pk2(hv.z, hv.z), hd3 = pk2(hv.w, hv.w);
    // row as 16 x 16B words; word (qq*4 + ol) holds logical pairs (2qq, 2qq+1) of this ol
    const ulonglong2* wr = reinterpret_cast<const ulonglong2*>(Wk + k * 32) + ol;
#pragma unroll
    for (int qq = 0; qq < 4; qq++) {
      ulonglong2 wp = wr[4 * qq];        // static immediate offset per qq
      acc[0][2*qq]   = fma2(hd0, wp.x, acc[0][2*qq]);
      acc[1][2*qq]   = fma2(hd1, wp.x, acc[1][2*qq]);
      acc[2][2*qq]   = fma2(hd2, wp.x, acc[2][2*qq]);
      acc[3][2*qq]   = fma2(hd3, wp.x, acc[3][2*qq]);
      acc[0][2*qq+1] = fma2(hd0, wp.y, acc[0][2*qq+1]);
      acc[1][2*qq+1] = fma2(hd1, wp.y, acc[1][2*qq+1]);
      acc[2][2*qq+1] = fma2(hd2, wp.y, acc[2][2*qq+1]);
      acc[3][2*qq+1] = fma2(hd3, wp.y, acc[3][2*qq+1]);
    }
  }
  // relu + in-place writeback (warp instruction stream orders all reads before writes)
#pragma unroll
  for (int p = 0; p < 8; p++) {
    int P = 8 * ol + p;
    float e[4], o[4];
#pragma unroll
    for (int n = 0; n < 4; n++) {
      unpk2(acc[n][p], e[n], o[n]);
      e[n] = fmaxf(e[n], 0.f); o[n] = fmaxf(o[n], 0.f);
    }
    int fe = 2 * P, fo = 2 * P + 1;
    *reinterpret_cast<float4*>(Hw + hidx(fe, 4 * nl)) = make_float4(e[0], e[1], e[2], e[3]);
    *reinterpret_cast<float4*>(Hw + hidx(fo, 4 * nl)) = make_float4(o[0], o[1], o[2], o[3]);
  }
}

__global__ void __launch_bounds__(THREADS, 1) dgcnn_kernel(
    const float* __restrict__ x,
    const float* __restrict__ W1, const float* __restrict__ b1,
    const float* __restrict__ W2, const float* __restrict__ b2,
    const float* __restrict__ W3, const float* __restrict__ b3,
    const float* __restrict__ W4, const float* __restrict__ b4,
    const float* __restrict__ cw1, const float* __restrict__ cb1,
    const float* __restrict__ cw2, const float* __restrict__ cb2,
    const float* __restrict__ Wo, const float* __restrict__ bo,
    float* __restrict__ out, int G, int P)
{
  extern __shared__ __align__(16) char smem_raw[];
  Smem& s = *reinterpret_cast<Smem*>(smem_raw);
  const int tid  = threadIdx.x;
  const int w    = tid >> 5;
  const int lane = tid & 31;

  // ---- Stage packed weights once per block ----
  for (int idx = tid; idx < 3 * 64 * 32; idx += THREADS) {
    int l = idx >> 11, rem = idx & 2047, k = rem >> 5, p = rem & 31;
    const float* Wg = (l == 0) ? W1 : (l == 1) ? W2 : W3;
    // logical pair p = ol*8 + qq*2 + par  ->  physical slot qq*8 + ol*2 + par
    int ol = p >> 3, qq = (p >> 1) & 3, par = p & 1;
    int phys = qq * 8 + ol * 2 + par;
    s.Wp[l][k][phys] = make_float2(Wg[(2 * p) * 64 + k], Wg[(2 * p + 1) * 64 + k]);
  }
  for (int idx = tid; idx < 64 * 20; idx += THREADS) {
    int k = idx / 20, p = idx % 20;
    s.Wp4[k][p] = (p < 17)
        ? make_float2(W4[(2 * p) * 64 + k], W4[(2 * p + 1) * 64 + k])
        : make_float2(0.f, 0.f);
  }
  if (tid < 32) {
    s.Bp[0][tid] = make_float2(b1[2 * tid], b1[2 * tid + 1]);
    s.Bp[1][tid] = make_float2(b2[2 * tid], b2[2 * tid + 1]);
    s.Bp[2][tid] = make_float2(b3[2 * tid], b3[2 * tid + 1]);
  }
  if (tid < 20)
    s.Bp4[tid] = (tid < 17) ? make_float2(b4[2 * tid], b4[2 * tid + 1])
                            : make_float2(0.f, 0.f);
  for (int i = tid; i < 80; i += THREADS) { int q = i >> 4, c = i & 15; s.cw1t[q][c] = cw1[c * 5 + q]; }
  if (tid < 16)  s.cb1[tid] = cb1[tid];
  for (int i = tid; i < 2560; i += THREADS) {
    int ci = i / 160, r = i % 160, q = r >> 5, c2 = r & 31;
    s.cw2t[ci][q][c2] = cw2[(c2 * 16 + ci) * 5 + q];
  }
  if (tid < 32)  s.cb2[tid] = cb2[tid];
  for (int i = tid; i < 704; i += THREADS) s.Wo[i] = Wo[i];
  if (tid < 2)   s.bo2[tid] = bo[tid];
  __syncthreads();

  const int kc = (P < 30) ? P : 30;
  const float inv = 1.f / (float)kc;
  float* Hw = s.H[w];
  const int nl8 = lane & 7,  ol8 = lane >> 3;   // layers 1-3 mapping
  const int nl4 = lane & 15, ol4 = lane >> 4;   // layer-4 mapping

  for (int g = blockIdx.x * NW + w; g < G; g += GRID * NW) {
    // ---- Load x rows into H (k-major, swizzled); pad nodes -> 0 ----
    {
      int src = (lane < kc) ? lane : 0;
      const float4* xr = reinterpret_cast<const float4*>(x + ((size_t)g * P + src) * 64);
      bool act = lane < kc;
#pragma unroll
      for (int q = 0; q < 16; q++) {
        float4 v = act ? xr[q] : make_float4(0.f, 0.f, 0.f, 0.f);
        int k0 = 4 * q;
        Hw[hidx(k0 + 0, lane)] = v.x;
        Hw[hidx(k0 + 1, lane)] = v.y;
        Hw[hidx(k0 + 2, lane)] = v.z;
        Hw[hidx(k0 + 3, lane)] = v.w;
      }
    }
    __syncwarp();

    // ---- Layers 1-3 ----
    mlp8x4(&s.Wp[0][0][0], s.Bp[0], Hw, nl8, ol8);
    mlp8x4(&s.Wp[1][0][0], s.Bp[1], Hw, nl8, ol8);
    mlp8x4(&s.Wp[2][0][0], s.Bp[2], Hw, nl8, ol8);

    // ---- Layer 4 (2 nodes x 10 pairs per lane) + pooling from accumulators ----
    {
      ull acc[2][10];
#pragma unroll
      for (int p = 0; p < 10; p++) {
        float2 b = s.Bp4[10 * ol4 + p];
        ull bb = pk2(b.x, b.y);
        acc[0][p] = bb; acc[1][p] = bb;
      }
#pragma unroll 8
      for (int k = 0; k < 64; k++) {
        const float2 hv = *reinterpret_cast<const float2*>(
            Hw + k * 32 + ((((nl4 >> 1) + (k >> 4)) & 7) << 2) + 2 * (nl4 & 1));
        ull h0 = pk2(hv.x, hv.x), h1 = pk2(hv.y, hv.y);
        const ulonglong2* wr = reinterpret_cast<const ulonglong2*>(&s.Wp4[k][10 * ol4]);
#pragma unroll
        for (int qq = 0; qq < 5; qq++) {
          ulonglong2 wp = wr[qq];
          acc[0][2*qq]   = fma2(h0, wp.x, acc[0][2*qq]);
          acc[1][2*qq]   = fma2(h1, wp.x, acc[1][2*qq]);
          acc[0][2*qq+1] = fma2(h0, wp.y, acc[0][2*qq+1]);
          acc[1][2*qq+1] = fma2(h1, wp.y, acc[1][2*qq+1]);
        }
      }
      // relu + node mask + mean-pool via butterfly
      float m0 = (2 * nl4     < kc) ? 1.f : 0.f;
      float m1 = (2 * nl4 + 1 < kc) ? 1.f : 0.f;
      float se[10], so[10];
#pragma unroll
      for (int p = 0; p < 10; p++) {
        float a0e, a0o, a1e, a1o;
        unpk2(acc[0][p], a0e, a0o);
        unpk2(acc[1][p], a1e, a1o);
        se[p] = m0 * fmaxf(a0e, 0.f) + m1 * fmaxf(a1e, 0.f);
        so[p] = m0 * fmaxf(a0o, 0.f) + m1 * fmaxf(a1o, 0.f);
      }
#pragma unroll
      for (int d = 1; d < 16; d <<= 1) {
#pragma unroll
        for (int p = 0; p < 10; p++) {
          se[p] += __shfl_xor_sync(0xffffffffu, se[p], d);
          so[p] += __shfl_xor_sync(0xffffffffu, so[p], d);
        }
      }
      if (nl4 == 0) {
#pragma unroll
        for (int p = 0; p < 10; p++) {
          int f = 20 * ol4 + 2 * p;
          if (f < 34) {
            s.pooled[w][f]     = se[p] * inv;
            s.pooled[w][f + 1] = so[p] * inv;
          }
        }
      }
    }
    __syncwarp();

    // ---- conv1 (16ch,k=5 -> 30) + ReLU + maxpool2 -> mps[16][15] ----
    {
      int c = lane & 15, h = lane >> 4;
      float wq[5];
#pragma unroll
      for (int q = 0; q < 5; q++) wq[q] = s.cw1t[q][c];
      float bc = s.cb1[c];
#pragma unroll
      for (int sIdx = 0; sIdx < 15; sIdx++) {
        int t = 2 * sIdx + h;
        float a = bc;
#pragma unroll
        for (int q = 0; q < 5; q++) a = fmaf(wq[q], s.pooled[w][t + q], a);
        a = fmaxf(a, 0.f);
        float mv = fmaxf(a, __shfl_xor_sync(0xffffffffu, a, 16));
        if (h == 0) s.mps[w][c][sIdx] = mv;
      }
    }
    __syncwarp();

    // ---- conv2 (32ch,16in,k=5 -> 11) + ReLU in registers; FC 352->2 fused ----
    {
      int c2 = lane;
      float a11[11];
#pragma unroll
      for (int t = 0; t < 11; t++) a11[t] = s.cb2[c2];
#pragma unroll
      for (int ci = 0; ci < 16; ci++) {
        const float4* mr = reinterpret_cast<const float4*>(&s.mps[w][ci][0]);
        float4 A = mr[0], B = mr[1], C = mr[2], D = mr[3];
        float m[16] = {A.x,A.y,A.z,A.w, B.x,B.y,B.z,B.w, C.x,C.y,C.z,C.w, D.x,D.y,D.z,D.w};
#pragma unroll
        for (int q = 0; q < 5; q++) {
          float wv = s.cw2t[ci][q][c2];
#pragma unroll
          for (int t = 0; t < 11; t++) a11[t] = fmaf(wv, m[t + q], a11[t]);
        }
      }
      float s0 = 0.f, s1 = 0.f;
#pragma unroll
      for (int t = 0; t < 11; t++) {
        float c = fmaxf(a11[t], 0.f);
        s0 = fmaf(s.Wo[c2 * 11 + t], c, s0);
        s1 = fmaf(s.Wo[352 + c2 * 11 + t], c, s1);
      }
#pragma unroll
      for (int d = 16; d > 0; d >>= 1) {
        s0 += __shfl_xor_sync(0xffffffffu, s0, d);
        s1 += __shfl_xor_sync(0xffffffffu, s1, d);
      }
      if (lane == 0) {
        out[g * 2 + 0] = s0 + s.bo2[0];
        out[g * 2 + 1] = s1 + s.bo2[1];
      }
    }
    __syncwarp();
  }
}

extern "C" void kernel_launch(void* const* d_in, const int* in_sizes, int n_in,
                              void* d_out, int out_size) {
  const float* x   = (const float*)d_in[0];
  // d_in[1] = edge_index (unused by reference), d_in[2] = batch (i // (N/G))
  const float* W1  = (const float*)d_in[3];
  const float* b1  = (const float*)d_in[4];
  const float* W2  = (const float*)d_in[5];
  const float* b2  = (const float*)d_in[6];
  const float* W3  = (const float*)d_in[7];
  const float* b3  = (const float*)d_in[8];
  const float* W4  = (const float*)d_in[9];
  const float* b4  = (const float*)d_in[10];
  const float* cw1 = (const float*)d_in[11];
  const float* cb1 = (const float*)d_in[12];
  const float* cw2 = (const float*)d_in[13];
  const float* cb2 = (const float*)d_in[14];
  const float* Wo  = (const float*)d_in[15];
  const float* bo  = (const float*)d_in[16];
  float* out = (float*)d_out;

  int G = out_size / 2;       // 10000
  int N = in_sizes[0] / 64;   // 1000000
  int P = N / G;              // 100

  int smem = (int)sizeof(Smem);
  cudaFuncSetAttribute(dgcnn_kernel, cudaFuncAttributeMaxDynamicSharedMemorySize, smem);

  dgcnn_kernel<<<GRID, THREADS, smem>>>(x, W1, b1, W2, b2, W3, b3, W4, b4,
                                        cw1, cb1, cw2, cb2, Wo, bo, out, G, P);
}

// round 7
// speedup vs baseline: 1.6583x; 1.6583x over previous
#include <cuda_runtime.h>
#include <cstdint>

#define THREADS 384
#define NW 12           // warps per block (3 per SMSP)
#define GRID 152

typedef unsigned long long ull;

__device__ __forceinline__ ull pk2(float lo, float hi) {
  ull r; asm("mov.b64 %0, {%1, %2};" : "=l"(r) : "f"(lo), "f"(hi)); return r;
}
__device__ __forceinline__ void unpk2(ull v, float& lo, float& hi) {
  asm("mov.b64 {%0, %1}, %2;" : "=f"(lo), "=f"(hi) : "l"(v));
}
__device__ __forceinline__ ull fma2(ull a, ull b, ull c) {
  ull d; asm("fma.rn.f32x2 %0, %1, %2, %3;" : "=l"(d) : "l"(a), "l"(b), "l"(c)); return d;
}

// ~203 KB dynamic shared memory, 1 block (12 warps) per SM.
struct Smem {
  alignas(16) float2 Wp[3][64][32];    // layers 1-3: Wp[l][k][P] = (W[2P][k], W[2P+1][k])
  alignas(16) float2 Wp4[64][20];      // layer 4: pairs 0..16 real (34 outs), 17..19 zero
  alignas(16) float2 Bp[3][32];
  alignas(16) float2 Bp4[20];
  float  cw1t[5][16];      // [q][c]   (lane-distinct reads)
  float  cb1[16];
  float  cw2t[16][5][32];  // [ci][q][c2]
  float  cb2[32];
  float  Wo[704];
  float  bo2[2];
  alignas(16) float  H[NW][64 * 32];   // per-warp activation tile, k-major, bank-swizzled
  alignas(16) float  pooled[NW][40];
  alignas(16) float  mps[NW][16][16];  // mp rows padded 15->16 (float4-aligned)
  alignas(16) float  c2s[NW][352];
};

// swizzled float-index of H element (row k / feature f, float column c 0..31)
__device__ __forceinline__ int hidx(int k, int c) {
  return k * 32 + ((((c >> 2) + (k >> 4)) & 7) << 2) + (c & 3);
}

// Layers 1-3: warp covers 32 nodes x 64 outputs; lane tile = 4 nodes x 8 pairs.
__device__ __forceinline__ void mlp8x4(const float2* __restrict__ Wk,  // [64][32]
                                       const float2* __restrict__ Bp,  // [32]
                                       float* __restrict__ Hw,         // [64*32]
                                       int nl, int ol) {
  ull acc[4][8];
#pragma unroll
  for (int p = 0; p < 8; p++) {
    float2 b = Bp[8 * ol + p];
    ull bb = pk2(b.x, b.y);
#pragma unroll
    for (int n = 0; n < 4; n++) acc[n][p] = bb;
  }
#pragma unroll 8
  for (int k = 0; k < 64; k++) {
    const float4 hv = *reinterpret_cast<const float4*>(Hw + hidx(k, 4 * nl));
    ull hd0 = pk2(hv.x, hv.x), hd1 = pk2(hv.y, hv.y);
    ull hd2 = pk2(hv.z, hv.z), hd3 = pk2(hv.w, hv.w);
    const ulonglong2* wr = reinterpret_cast<const ulonglong2*>(Wk + k * 32 + 8 * ol);
#pragma unroll
    for (int qq = 0; qq < 4; qq++) {
      ulonglong2 wp = wr[qq];
      acc[0][2*qq]   = fma2(hd0, wp.x, acc[0][2*qq]);
      acc[1][2*qq]   = fma2(hd1, wp.x, acc[1][2*qq]);
      acc[2][2*qq]   = fma2(hd2, wp.x, acc[2][2*qq]);
      acc[3][2*qq]   = fma2(hd3, wp.x, acc[3][2*qq]);
      acc[0][2*qq+1] = fma2(hd0, wp.y, acc[0][2*qq+1]);
      acc[1][2*qq+1] = fma2(hd1, wp.y, acc[1][2*qq+1]);
      acc[2][2*qq+1] = fma2(hd2, wp.y, acc[2][2*qq+1]);
      acc[3][2*qq+1] = fma2(hd3, wp.y, acc[3][2*qq+1]);
    }
  }
  // relu + in-place writeback (warp instruction stream orders all reads before writes)
#pragma unroll
  for (int p = 0; p < 8; p++) {
    int P = 8 * ol + p;
    float e[4], o[4];
#pragma unroll
    for (int n = 0; n < 4; n++) {
      unpk2(acc[n][p], e[n], o[n]);
      e[n] = fmaxf(e[n], 0.f); o[n] = fmaxf(o[n], 0.f);
    }
    int fe = 2 * P, fo = 2 * P + 1;
    *reinterpret_cast<float4*>(Hw + hidx(fe, 4 * nl)) = make_float4(e[0], e[1], e[2], e[3]);
    *reinterpret_cast<float4*>(Hw + hidx(fo, 4 * nl)) = make_float4(o[0], o[1], o[2], o[3]);
  }
}

__global__ void __launch_bounds__(THREADS, 1) dgcnn_kernel(
    const float* __restrict__ x,
    const float* __restrict__ W1, const float* __restrict__ b1,
    const float* __restrict__ W2, const float* __restrict__ b2,
    const float* __restrict__ W3, const float* __restrict__ b3,
    const float* __restrict__ W4, const float* __restrict__ b4,
    const float* __restrict__ cw1, const float* __restrict__ cb1,
    const float* __restrict__ cw2, const float* __restrict__ cb2,
    const float* __restrict__ Wo, const float* __restrict__ bo,
    float* __restrict__ out, int G, int P)
{
  extern __shared__ __align__(16) char smem_raw[];
  Smem& s = *reinterpret_cast<Smem*>(smem_raw);
  const int tid  = threadIdx.x;
  const int w    = tid >> 5;
  const int lane = tid & 31;

  // ---- Stage packed weights once per block ----
  for (int idx = tid; idx < 3 * 64 * 32; idx += THREADS) {
    int l = idx >> 11, rem = idx & 2047, k = rem >> 5, p = rem & 31;
    const float* Wg = (l == 0) ? W1 : (l == 1) ? W2 : W3;
    s.Wp[l][k][p] = make_float2(Wg[(2 * p) * 64 + k], Wg[(2 * p + 1) * 64 + k]);
  }
  for (int idx = tid; idx < 64 * 20; idx += THREADS) {
    int k = idx / 20, p = idx % 20;
    s.Wp4[k][p] = (p < 17)
        ? make_float2(W4[(2 * p) * 64 + k], W4[(2 * p + 1) * 64 + k])
        : make_float2(0.f, 0.f);
  }
  if (tid < 32) {
    s.Bp[0][tid] = make_float2(b1[2 * tid], b1[2 * tid + 1]);
    s.Bp[1][tid] = make_float2(b2[2 * tid], b2[2 * tid + 1]);
    s.Bp[2][tid] = make_float2(b3[2 * tid], b3[2 * tid + 1]);
  }
  if (tid < 20)
    s.Bp4[tid] = (tid < 17) ? make_float2(b4[2 * tid], b4[2 * tid + 1])
                            : make_float2(0.f, 0.f);
  for (int i = tid; i < 80; i += THREADS) { int q = i >> 4, c = i & 15; s.cw1t[q][c] = cw1[c * 5 + q]; }
  if (tid < 16)  s.cb1[tid] = cb1[tid];
  for (int i = tid; i < 2560; i += THREADS) {
    int ci = i / 160, r = i % 160, q = r >> 5, c2 = r & 31;
    s.cw2t[ci][q][c2] = cw2[(c2 * 16 + ci) * 5 + q];
  }
  if (tid < 32)  s.cb2[tid] = cb2[tid];
  for (int i = tid; i < 704; i += THREADS) s.Wo[i] = Wo[i];
  if (tid < 2)   s.bo2[tid] = bo[tid];
  __syncthreads();

  const int kc = (P < 30) ? P : 30;
  const float inv = 1.f / (float)kc;
  float* Hw = s.H[w];
  const int nl8 = lane & 7,  ol8 = lane >> 3;   // layers 1-3 mapping
  const int nl4 = lane & 15, ol4 = lane >> 4;   // layer-4 mapping

  for (int g = blockIdx.x * NW + w; g < G; g += GRID * NW) {
    // ---- Load x rows into H (k-major, swizzled); pad nodes -> 0 ----
    {
      int src = (lane < kc) ? lane : 0;
      const float4* xr = reinterpret_cast<const float4*>(x + ((size_t)g * P + src) * 64);
      bool act = lane < kc;
#pragma unroll
      for (int q = 0; q < 16; q++) {
        float4 v = act ? xr[q] : make_float4(0.f, 0.f, 0.f, 0.f);
        int k0 = 4 * q;
        Hw[hidx(k0 + 0, lane)] = v.x;
        Hw[hidx(k0 + 1, lane)] = v.y;
        Hw[hidx(k0 + 2, lane)] = v.z;
        Hw[hidx(k0 + 3, lane)] = v.w;
      }
    }
    __syncwarp();

    // ---- Layers 1-3 ----
    mlp8x4(&s.Wp[0][0][0], s.Bp[0], Hw, nl8, ol8);
    mlp8x4(&s.Wp[1][0][0], s.Bp[1], Hw, nl8, ol8);
    mlp8x4(&s.Wp[2][0][0], s.Bp[2], Hw, nl8, ol8);

    // ---- Layer 4 (2 nodes x 10 pairs per lane) + pooling from accumulators ----
    {
      ull acc[2][10];
#pragma unroll
      for (int p = 0; p < 10; p++) {
        float2 b = s.Bp4[10 * ol4 + p];
        ull bb = pk2(b.x, b.y);
        acc[0][p] = bb; acc[1][p] = bb;
      }
#pragma unroll 8
      for (int k = 0; k < 64; k++) {
        const float2 hv = *reinterpret_cast<const float2*>(
            Hw + k * 32 + ((((nl4 >> 1) + (k >> 4)) & 7) << 2) + 2 * (nl4 & 1));
        ull h0 = pk2(hv.x, hv.x), h1 = pk2(hv.y, hv.y);
        const ulonglong2* wr = reinterpret_cast<const ulonglong2*>(&s.Wp4[k][10 * ol4]);
#pragma unroll
        for (int qq = 0; qq < 5; qq++) {
          ulonglong2 wp = wr[qq];
          acc[0][2*qq]   = fma2(h0, wp.x, acc[0][2*qq]);
          acc[1][2*qq]   = fma2(h1, wp.x, acc[1][2*qq]);
          acc[0][2*qq+1] = fma2(h0, wp.y, acc[0][2*qq+1]);
          acc[1][2*qq+1] = fma2(h1, wp.y, acc[1][2*qq+1]);
        }
      }
      // relu + node mask + mean-pool via butterfly
      float m0 = (2 * nl4     < kc) ? 1.f : 0.f;
      float m1 = (2 * nl4 + 1 < kc) ? 1.f : 0.f;
      float se[10], so[10];
#pragma unroll
      for (int p = 0; p < 10; p++) {
        float a0e, a0o, a1e, a1o;
        unpk2(acc[0][p], a0e, a0o);
        unpk2(acc[1][p], a1e, a1o);
        se[p] = m0 * fmaxf(a0e, 0.f) + m1 * fmaxf(a1e, 0.f);
        so[p] = m0 * fmaxf(a0o, 0.f) + m1 * fmaxf(a1o, 0.f);
      }
#pragma unroll
      for (int d = 1; d < 16; d <<= 1) {
#pragma unroll
        for (int p = 0; p < 10; p++) {
          se[p] += __shfl_xor_sync(0xffffffffu, se[p], d);
          so[p] += __shfl_xor_sync(0xffffffffu, so[p], d);
        }
      }
      if (nl4 == 0) {
#pragma unroll
        for (int p = 0; p < 10; p++) {
          int f = 20 * ol4 + 2 * p;
          if (f < 34) {
            s.pooled[w][f]     = se[p] * inv;
            s.pooled[w][f + 1] = so[p] * inv;
          }
        }
      }
    }
    __syncwarp();

    // ---- conv1 (16ch,k=5 -> 30) + ReLU + maxpool2 -> mps[16][15] ----
    {
      int c = lane & 15, h = lane >> 4;
      float wq[5];
#pragma unroll
      for (int q = 0; q < 5; q++) wq[q] = s.cw1t[q][c];
      float bc = s.cb1[c];
#pragma unroll
      for (int sIdx = 0; sIdx < 15; sIdx++) {
        int t = 2 * sIdx + h;
        float a = bc;
#pragma unroll
        for (int q = 0; q < 5; q++) a = fmaf(wq[q], s.pooled[w][t + q], a);
        a = fmaxf(a, 0.f);
        float mv = fmaxf(a, __shfl_xor_sync(0xffffffffu, a, 16));
        if (h == 0) s.mps[w][c][sIdx] = mv;
      }
    }
    __syncwarp();

    // ---- conv2 (32ch,16in,k=5 -> 11) + ReLU ----
    {
      int c2 = lane;
      float a11[11];
#pragma unroll
      for (int t = 0; t < 11; t++) a11[t] = s.cb2[c2];
#pragma unroll
      for (int ci = 0; ci < 16; ci++) {
        const float4* mr = reinterpret_cast<const float4*>(&s.mps[w][ci][0]);
        float4 A = mr[0], B = mr[1], C = mr[2], D = mr[3];
        float m[16] = {A.x,A.y,A.z,A.w, B.x,B.y,B.z,B.w, C.x,C.y,C.z,C.w, D.x,D.y,D.z,D.w};
#pragma unroll
        for (int q = 0; q < 5; q++) {
          float wv = s.cw2t[ci][q][c2];
#pragma unroll
          for (int t = 0; t < 11; t++) a11[t] = fmaf(wv, m[t + q], a11[t]);
        }
      }
#pragma unroll
      for (int t = 0; t < 11; t++) s.c2s[w][c2 * 11 + t] = fmaxf(a11[t], 0.f);
    }
    __syncwarp();

    // ---- FC 352 -> 2 ----
    {
      float s0 = 0.f, s1 = 0.f;
#pragma unroll
      for (int j = 0; j < 11; j++) {
        int i = lane + 32 * j;
        float c = s.c2s[w][i];
        s0 = fmaf(s.Wo[i], c, s0);
        s1 = fmaf(s.Wo[352 + i], c, s1);
      }
#pragma unroll
      for (int d = 16; d > 0; d >>= 1) {
        s0 += __shfl_xor_sync(0xffffffffu, s0, d);
        s1 += __shfl_xor_sync(0xffffffffu, s1, d);
      }
      if (lane == 0) {
        out[g * 2 + 0] = s0 + s.bo2[0];
        out[g * 2 + 1] = s1 + s.bo2[1];
      }
    }
    __syncwarp();
  }
}

extern "C" void kernel_launch(void* const* d_in, const int* in_sizes, int n_in,
                              void* d_out, int out_size) {
  const float* x   = (const float*)d_in[0];
  // d_in[1] = edge_index (unused by reference), d_in[2] = batch (i // (N/G))
  const float* W1  = (const float*)d_in[3];
  const float* b1  = (const float*)d_in[4];
  const float* W2  = (const float*)d_in[5];
  const float* b2  = (const float*)d_in[6];
  const float* W3  = (const float*)d_in[7];
  const float* b3  = (const float*)d_in[8];
  const float* W4  = (const float*)d_in[9];
  const float* b4  = (const float*)d_in[10];
  const float* cw1 = (const float*)d_in[11];
  const float* cb1 = (const float*)d_in[12];
  const float* cw2 = (const float*)d_in[13];
  const float* cb2 = (const float*)d_in[14];
  const float* Wo  = (const float*)d_in[15];
  const float* bo  = (const float*)d_in[16];
  float* out = (float*)d_out;

  int G = out_size / 2;       // 10000
  int N = in_sizes[0] / 64;   // 1000000
  int P = N / G;              // 100

  int smem = (int)sizeof(Smem);
  cudaFuncSetAttribute(dgcnn_kernel, cudaFuncAttributeMaxDynamicSharedMemorySize, smem);

  dgcnn_kernel<<<GRID, THREADS, smem>>>(x, W1, b1, W2, b2, W3, b3, W4, b4,
                                        cw1, cb1, cw2, cb2, Wo, bo, out, G, P);
}